// round 7
// baseline (speedup 1.0000x reference)
#include <cuda_runtime.h>
#include <cuda_fp16.h>
#include <cstdint>

#define NROWS 65536
#define KCENT 4096
#define DIM   256

// ------------------------- device scratch ----------------------------------
__device__ float g_c2[KCENT];
__device__ float g_segsum[KCENT * DIM];
__device__ int   g_segcnt[KCENT];
__device__ int   g_labels[2 * NROWS];   // [half][row]
__device__ float g_minq[2 * NROWS];
__device__ float g_loss;
// fp16 split (h, m = x-h UNSCALED), fragment-ready: [row][8 chunks][32 words]
__device__ uint32_t g_xf2[(size_t)NROWS * 256];   // 64 MB
__device__ uint32_t g_cf2[(size_t)KCENT * 256];   // 4 MB

// ------------------------- helpers ------------------------------------------
__device__ __forceinline__ uint32_t smem_u32(const void* p) {
    uint32_t a;
    asm("{ .reg .u64 t; cvta.to.shared.u64 t, %1; cvt.u32.u64 %0, t; }" : "=r"(a) : "l"(p));
    return a;
}

__device__ __forceinline__ void mma16816(float* d,
    uint32_t a0, uint32_t a1, uint32_t a2, uint32_t a3, uint32_t b0, uint32_t b1)
{
    asm volatile(
        "mma.sync.aligned.m16n8k16.row.col.f32.f16.f16.f32 "
        "{%0,%1,%2,%3}, {%4,%5,%6,%7}, {%8,%9}, {%0,%1,%2,%3};"
        : "+f"(d[0]), "+f"(d[1]), "+f"(d[2]), "+f"(d[3])
        : "r"(a0), "r"(a1), "r"(a2), "r"(a3), "r"(b0), "r"(b1));
}

__device__ __forceinline__ uint4 lds128(uint32_t byte_addr) {
    uint4 v;
    asm volatile("ld.shared.v4.u32 {%0,%1,%2,%3}, [%4];"
        : "=r"(v.x), "=r"(v.y), "=r"(v.z), "=r"(v.w) : "r"(byte_addr));
    return v;
}

__device__ __forceinline__ void cp16(uint32_t smem_byte, const void* gptr) {
    asm volatile("cp.async.cg.shared.global [%0], [%1], 16;" :: "r"(smem_byte), "l"(gptr));
}
#define CP_COMMIT() asm volatile("cp.async.commit_group;" ::: "memory")
#define CP_WAIT(n)  asm volatile("cp.async.wait_group %0;" :: "n"(n) : "memory")

__device__ __forceinline__ uint32_t packh(float a, float b) {
    __half2 p = __halves2half2(__float2half_rn(a), __float2half_rn(b));
    return *(uint32_t*)&p;
}

// ---------------------------------------------------------------------------
__global__ void init_kernel(int KD, int K) {
    int i = blockIdx.x * blockDim.x + threadIdx.x;
    if (i < KD) g_segsum[i] = 0.0f;
    if (i < K)  g_segcnt[i] = 0;
    if (i == 0) g_loss = 0.0f;
}

__global__ void c2_kernel(const float* __restrict__ C, int D) {
    int k = blockIdx.x;
    int t = threadIdx.x;
    float s = 0.0f;
    for (int d = t * 4; d < D; d += blockDim.x * 4) {
        float4 v = *(const float4*)(C + (size_t)k * D + d);
        s += v.x * v.x + v.y * v.y + v.z * v.z + v.w * v.w;
    }
    #pragma unroll
    for (int o = 16; o; o >>= 1) s += __shfl_down_sync(0xffffffffu, s, o);
    __shared__ float ws[2];
    if ((t & 31) == 0) ws[t >> 5] = s;
    __syncthreads();
    if (t == 0) g_c2[k] = ws[0] + ws[1];
}

// fp32 -> fp16 (h, m = x-h) fragment-ready layout.
__global__ void split_f16_kernel(const float* __restrict__ src,
                                 uint32_t* __restrict__ dst, int rows) {
    int t = blockIdx.x * blockDim.x + threadIdx.x;
    if (t >= rows * 16) return;
    int row = t >> 4;
    int b16 = t & 15;
    int c   = b16 >> 1;
    int blk = b16 & 1;
    const float* s = src + (size_t)row * DIM + c * 32 + blk * 16;
    float x[16];
    #pragma unroll
    for (int i = 0; i < 4; i++) *(float4*)(x + i * 4) = *(const float4*)(s + i * 4);
    float h[16], m[16];
    #pragma unroll
    for (int i = 0; i < 16; i++) {
        h[i] = __half2float(__float2half_rn(x[i]));
        m[i] = x[i] - h[i];
    }
    uint32_t w[16];
    #pragma unroll
    for (int q = 0; q < 4; q++) {
        w[4 * q + 0] = packh(h[2 * q],     h[2 * q + 1]);
        w[4 * q + 1] = packh(h[2 * q + 8], h[2 * q + 9]);
        w[4 * q + 2] = packh(m[2 * q],     m[2 * q + 1]);
        w[4 * q + 3] = packh(m[2 * q + 8], m[2 * q + 9]);
    }
    uint32_t* d = dst + (size_t)row * 256 + c * 32 + (((row & 1) << 4) ^ (blk << 4));
    #pragma unroll
    for (int i = 0; i < 4; i++) *(uint4*)(d + i * 4) = *(uint4*)(w + i * 4);
}

// ---------------------------------------------------------------------------
// Assign: fp16 split GEMM + argmin. 512 threads (16 warps), warp tile 32x64,
// macro tile 128 rows x 256 cols (8 tiles per CTA half). A resident (128 KB),
// B double-buffered kc=32 chunks (32 KB each) via cp.async. Single fp32 acc.
// ---------------------------------------------------------------------------
#define A_WORDS 32768            // 128 KB
#define B_WORDS 8192             // 32 KB per buffer
#define SM_TOTAL_BYTES ((A_WORDS + 2 * B_WORDS) * 4 + 4096)

__global__ __launch_bounds__(512, 1) void assign_mma_kernel() {
    extern __shared__ uint32_t sm[];
    uint32_t* As = sm;
    float* redv = (float*)(sm + A_WORDS + 2 * B_WORDS);
    int*   redi = (int*)(redv + 512);

    int tid  = threadIdx.x;
    int lane = tid & 31;
    int wid  = tid >> 5;
    int wm   = wid & 3;            // row group (x32)
    int wn   = wid >> 2;           // col group (x64), 0..3
    int g    = lane >> 2;
    int t4   = lane & 3;
    int colHalf = blockIdx.x & 1;
    int rowBase = (blockIdx.x >> 1) * 128;
    int colBase = colHalf * 2048;

    uint32_t sbA = smem_u32(As);
    uint32_t sbB = sbA + A_WORDS * 4;
    const uint4* xf = (const uint4*)g_xf2;   // row = 64 uint4
    const uint4* cf = (const uint4*)g_cf2;

    // ---- B chunk copy: chunk q = tile (q>>3) of this half, kpart j = q&7 ----
    auto copy_chunk = [&](int q) {
        int nBase = colBase + (q >> 3) * 256;
        int j = q & 7;
        uint32_t dstb = sbB + (q & 1) * (B_WORDS * 4);
        #pragma unroll
        for (int i = 0; i < 4; i++) {
            int idx = tid + i * 512;              // 0..2047
            int r = idx >> 3, rem = idx & 7;
            cp16(dstb + idx * 16, cf + (size_t)(nBase + r) * 64 + j * 8 + rem);
        }
        CP_COMMIT();
    };

    copy_chunk(0);
    copy_chunk(1);

    // ---- A resident copy ----
    #pragma unroll 4
    for (int i = 0; i < 16; i++) {
        int idx = tid + i * 512;                  // 0..8191
        ((uint4*)As)[idx] = xf[(size_t)(rowBase + (idx >> 6)) * 64 + (idx & 63)];
    }

    float acc[2][8][4];
    #pragma unroll
    for (int mt = 0; mt < 2; mt++)
        #pragma unroll
        for (int nt = 0; nt < 8; nt++)
            #pragma unroll
            for (int j = 0; j < 4; j++) acc[mt][nt][j] = 0.0f;

    float minv[4];
    int   mini[4];
    #pragma unroll
    for (int s = 0; s < 4; s++) { minv[s] = 3.0e38f; mini[s] = 0; }

    for (int q = 0; q < 64; q++) {
        if (q < 62) CP_WAIT(1); else CP_WAIT(0);
        __syncthreads();

        int j = q & 7;
        uint32_t bufb = sbB + (q & 1) * (B_WORDS * 4);

        #pragma unroll
        for (int kk = 0; kk < 2; kk++) {
            uint4 qa[2][2];
            #pragma unroll
            for (int mt = 0; mt < 2; mt++)
                #pragma unroll
                for (int rh = 0; rh < 2; rh++) {
                    int r = wm * 32 + mt * 16 + g + rh * 8;
                    uint32_t w = r * 256 + j * 32 + (((r & 1) << 4) ^ (kk << 4)) + t4 * 4;
                    qa[mt][rh] = lds128(sbA + w * 4);
                }

            #pragma unroll
            for (int h = 0; h < 2; h++) {
                uint4 qb[4];
                #pragma unroll
                for (int n2 = 0; n2 < 4; n2++) {
                    int n = wn * 64 + (h * 4 + n2) * 8 + g;
                    uint32_t w = n * 32 + (((n & 1) << 4) ^ (kk << 4)) + t4 * 4;
                    qb[n2] = lds128(bufb + w * 4);
                }
                // pass 1: h*h
                #pragma unroll
                for (int n2 = 0; n2 < 4; n2++)
                    #pragma unroll
                    for (int mt = 0; mt < 2; mt++)
                        mma16816(acc[mt][h * 4 + n2],
                                 qa[mt][0].x, qa[mt][1].x, qa[mt][0].y, qa[mt][1].y,
                                 qb[n2].x, qb[n2].y);
                // pass 2: m*h
                #pragma unroll
                for (int n2 = 0; n2 < 4; n2++)
                    #pragma unroll
                    for (int mt = 0; mt < 2; mt++)
                        mma16816(acc[mt][h * 4 + n2],
                                 qa[mt][0].z, qa[mt][1].z, qa[mt][0].w, qa[mt][1].w,
                                 qb[n2].x, qb[n2].y);
                // pass 3: h*m
                #pragma unroll
                for (int n2 = 0; n2 < 4; n2++)
                    #pragma unroll
                    for (int mt = 0; mt < 2; mt++)
                        mma16816(acc[mt][h * 4 + n2],
                                 qa[mt][0].x, qa[mt][1].x, qa[mt][0].y, qa[mt][1].y,
                                 qb[n2].z, qb[n2].w);
            }
        }

        if ((q & 7) == 7) {
            int nBase = colBase + (q >> 3) * 256;
            #pragma unroll
            for (int nt = 0; nt < 8; nt++) {
                int lc = wn * 64 + nt * 8 + 2 * t4;
                float c2a = __ldg(&g_c2[nBase + lc]);
                float c2b = __ldg(&g_c2[nBase + lc + 1]);
                int col = nBase + lc;
                #pragma unroll
                for (int mt = 0; mt < 2; mt++) {
                    float q0 = fmaf(-2.0f, acc[mt][nt][0], c2a);
                    float q1 = fmaf(-2.0f, acc[mt][nt][1], c2b);
                    float q2 = fmaf(-2.0f, acc[mt][nt][2], c2a);
                    float q3 = fmaf(-2.0f, acc[mt][nt][3], c2b);
                    int s0 = mt * 2, s1 = mt * 2 + 1;
                    if (q0 < minv[s0]) { minv[s0] = q0; mini[s0] = col; }
                    if (q1 < minv[s0]) { minv[s0] = q1; mini[s0] = col + 1; }
                    if (q2 < minv[s1]) { minv[s1] = q2; mini[s1] = col; }
                    if (q3 < minv[s1]) { minv[s1] = q3; mini[s1] = col + 1; }
                    acc[mt][nt][0] = 0.0f; acc[mt][nt][1] = 0.0f;
                    acc[mt][nt][2] = 0.0f; acc[mt][nt][3] = 0.0f;
                }
            }
        }
        __syncthreads();
        if (q < 62) copy_chunk(q + 2);
    }

    // ---- argmin reduce across t4 lanes, then across the 4 wn groups ----
    #pragma unroll
    for (int s = 1; s <= 2; s <<= 1) {
        #pragma unroll
        for (int sl = 0; sl < 4; sl++) {
            float ov = __shfl_xor_sync(0xffffffffu, minv[sl], s);
            int   oi = __shfl_xor_sync(0xffffffffu, mini[sl], s);
            if (ov < minv[sl] || (ov == minv[sl] && oi < mini[sl])) {
                minv[sl] = ov; mini[sl] = oi;
            }
        }
    }
    if (t4 == 0) {
        #pragma unroll
        for (int sl = 0; sl < 4; sl++) {
            int rl = wm * 32 + (sl >> 1) * 16 + (sl & 1) * 8 + g;
            redv[rl * 4 + wn] = minv[sl];
            redi[rl * 4 + wn] = mini[sl];
        }
    }
    __syncthreads();
    if (tid < 128) {
        float v = redv[tid * 4];
        int   i = redi[tid * 4];
        #pragma unroll
        for (int c = 1; c < 4; c++) {
            float ov = redv[tid * 4 + c];
            int   oi = redi[tid * 4 + c];
            if (ov < v || (ov == v && oi < i)) { v = ov; i = oi; }
        }
        g_labels[colHalf * NROWS + rowBase + tid] = i;
        g_minq[colHalf * NROWS + rowBase + tid]   = v;
    }
}

// ---------------------------------------------------------------------------
__global__ __launch_bounds__(256) void scatter_kernel(
    const float* __restrict__ X, float* __restrict__ out_labels, int D)
{
    int r    = blockIdx.x * 4 + (threadIdx.x >> 6);
    int lane = threadIdx.x & 63;

    float v0 = g_minq[r],        v1 = g_minq[NROWS + r];
    int   l0 = g_labels[r],      l1 = g_labels[NROWS + r];
    int   lab;  float vmin;
    if (v1 < v0) { lab = l1; vmin = v1; } else { lab = l0; vmin = v0; }

    float4 v = *(const float4*)(X + (size_t)r * D + lane * 4);
    float* dst = g_segsum + (size_t)lab * D + lane * 4;
    atomicAdd(dst + 0, v.x);
    atomicAdd(dst + 1, v.y);
    atomicAdd(dst + 2, v.z);
    atomicAdd(dst + 3, v.w);

    float part = v.x * v.x + v.y * v.y + v.z * v.z + v.w * v.w;
    if (lane == 0) {
        part += vmin;
        atomicAdd(&g_segcnt[lab], 1);
        out_labels[r] = (float)lab;
    }

    #pragma unroll
    for (int o = 16; o; o >>= 1) part += __shfl_down_sync(0xffffffffu, part, o);
    __shared__ float ws[8];
    if ((threadIdx.x & 31) == 0) ws[threadIdx.x >> 5] = part;
    __syncthreads();
    if (threadIdx.x < 8) {
        float s = ws[threadIdx.x];
        #pragma unroll
        for (int o = 4; o; o >>= 1) s += __shfl_down_sync(0xffu, s, o);
        if (threadIdx.x == 0) atomicAdd(&g_loss, s);
    }
}

// ---------------------------------------------------------------------------
__global__ void finalize_kernel(
    const float* __restrict__ centers, const int* __restrict__ counts,
    float* __restrict__ out_centers, float* __restrict__ out_counts,
    float* __restrict__ out_loss, int K, int D, float invN)
{
    int idx = blockIdx.x * blockDim.x + threadIdx.x;
    if (idx < K * D) {
        int k = idx / D;
        float c0  = (float)counts[k];
        float cnt = (float)g_segcnt[k];
        out_centers[idx] = (c0 * centers[idx] + g_segsum[idx]) / (c0 + cnt);
    }
    if (idx < K) out_counts[idx] = (float)(counts[idx] + g_segcnt[idx]);
    if (idx == 0) out_loss[0] = g_loss * invN;
}

// ---------------------------------------------------------------------------
extern "C" void kernel_launch(void* const* d_in, const int* in_sizes, int n_in,
                              void* d_out, int out_size)
{
    const float* X      = (const float*)d_in[0];
    const float* C      = (const float*)d_in[1];
    const int*   counts = (const int*)  d_in[2];

    const int N = NROWS, K = KCENT, D = DIM;
    const int KD = K * D;

    float* out         = (float*)d_out;
    float* out_labels  = out;
    float* out_centers = out + N;
    float* out_counts  = out + N + (size_t)KD;
    float* out_loss    = out_counts + K;

    static uint32_t* xf_ptr = nullptr;
    static uint32_t* cf_ptr = nullptr;
    static bool configured = false;
    if (!configured) {
        cudaGetSymbolAddress((void**)&xf_ptr, g_xf2);
        cudaGetSymbolAddress((void**)&cf_ptr, g_cf2);
        cudaFuncSetAttribute(assign_mma_kernel,
                             cudaFuncAttributeMaxDynamicSharedMemorySize,
                             SM_TOTAL_BYTES);
        configured = true;
    }

    init_kernel<<<(KD + 255) / 256, 256>>>(KD, K);
    c2_kernel<<<K, 64>>>(C, D);
    split_f16_kernel<<<(N * 16 + 255) / 256, 256>>>(X, xf_ptr, N);
    split_f16_kernel<<<(K * 16 + 255) / 256, 256>>>(C, cf_ptr, K);
    assign_mma_kernel<<<2 * (N / 128), 512, SM_TOTAL_BYTES>>>();
    scatter_kernel<<<N / 4, 256>>>(X, out_labels, D);
    finalize_kernel<<<(KD + 255) / 256, 256>>>(C, counts, out_centers, out_counts,
                                               out_loss, K, D, 1.0f / (float)N);
}